// round 17
// baseline (speedup 1.0000x reference)
#include <cuda_runtime.h>
#include <cuda_fp16.h>
#include <cstdint>

typedef unsigned long long ull;

#define DIN   4096
#define NM    8
#define NH    512
#define NOUT  10

// fp16 pre-converted W1 diagonal blocks: [m][512 rows][512 k]
__device__ __half g_w1h[8u * 512u * 512u];

// ---- dynamic smem layout (bytes): B-only 2-deep ring, 64-k chunks ----
#define STAGE_STRIDE 36864u      // B: 256 rows * 144B
#define T_B          0u
#define OFF_HBUF     73728u      // 128 * 132 * 4 = 67584
#define HPITCH       132
#define OFF_W2       141312u     // 512*12*4 = 24576
#define OFF_B1       165888u     // 2048
#define SMEM_TOTAL   167936u

static __device__ __forceinline__ uint32_t smem_u32(const void* p) {
    uint32_t a;
    asm("{ .reg .u64 t; cvta.to.shared.u64 t, %1; cvt.u32.u64 %0, t; }"
        : "=r"(a) : "l"(p));
    return a;
}
static __device__ __forceinline__ void ldsm4(uint32_t* r, uint32_t addr) {
    asm volatile("ldmatrix.sync.aligned.m8n8.x4.shared.b16 {%0,%1,%2,%3}, [%4];"
                 : "=r"(r[0]), "=r"(r[1]), "=r"(r[2]), "=r"(r[3]) : "r"(addr));
}
static __device__ __forceinline__ void mma16816f(float* d, const uint32_t* a,
                                                 uint32_t b0, uint32_t b1) {
    asm volatile("mma.sync.aligned.m16n8k16.row.col.f32.f16.f16.f32 "
                 "{%0,%1,%2,%3}, {%4,%5,%6,%7}, {%8,%9}, {%0,%1,%2,%3};"
                 : "+f"(d[0]), "+f"(d[1]), "+f"(d[2]), "+f"(d[3])
                 : "r"(a[0]), "r"(a[1]), "r"(a[2]), "r"(a[3]), "r"(b0), "r"(b1));
}
static __device__ __forceinline__ void cp16(uint32_t dst, const void* src) {
    asm volatile("cp.async.cg.shared.global [%0], [%1], 16;"
                 :: "r"(dst), "l"(src) : "memory");
}
static __device__ __forceinline__ void cp_commit() {
    asm volatile("cp.async.commit_group;" ::: "memory");
}
static __device__ __forceinline__ void cp_wait0() {
    asm volatile("cp.async.wait_group 0;" ::: "memory");
}
static __device__ __forceinline__ ull packdup(float v) {
    ull r;
    asm("mov.b64 %0, {%1, %1};" : "=l"(r) : "r"(__float_as_uint(v)));
    return r;
}
static __device__ __forceinline__ void fma2(ull& d, ull a, ull b) {
    asm("fma.rn.f32x2 %0, %1, %2, %0;" : "+l"(d) : "l"(a), "l"(b));
}
static __device__ __forceinline__ ull add2(ull a, ull b) {
    ull r;
    asm("add.rn.f32x2 %0, %1, %2;" : "=l"(r) : "l"(a), "l"(b));
    return r;
}
static __device__ __forceinline__ uint32_t packh2(float2 v) {
    __half2 h = __floats2half2_rn(v.x, v.y);
    return *(uint32_t*)&h;
}
static __device__ __forceinline__ void cvt4(float4 v, uint32_t& p01, uint32_t& p23) {
    __half2 a = __floats2half2_rn(v.x, v.y);
    __half2 b = __floats2half2_rn(v.z, v.w);
    p01 = *(uint32_t*)&a;
    p23 = *(uint32_t*)&b;
}

// -------- pre-pass: W1 diag blocks -> fp16 --------
__global__ __launch_bounds__(256)
void cvt_w1(const float* __restrict__ W1) {
    int g = blockIdx.x * 256 + threadIdx.x;
    int m = g >> 16;
    int rem = g & 65535;
    int r = rem >> 7;
    int c4 = rem & 127;
    float4 v = *(const float4*)(W1 + (size_t)(m * 512 + r) * DIN + m * 512 + c4 * 4);
    uint32_t p01, p23;
    cvt4(v, p01, p23);
    *(uint2*)(g_w1h + ((size_t)(m * 512 + r) * 512 + c4 * 4)) = make_uint2(p01, p23);
}

// A fragments straight from global fp32 x, converted in-register.
// Fragment layout (m16n8k16 row.col A): r0=(row,kp) r1=(row+8,kp) r2=(row,kp+8) r3=(row+8,kp+8)
static __device__ __forceinline__ void loadA_frags(const float* xA, int kb,
                                                   uint32_t af[4][4]) {
    #pragma unroll
    for (int i = 0; i < 4; i++) {
        const float* rp = xA + (size_t)(i * 16) * DIN + kb;
        float2 v0 = *(const float2*)(rp);
        float2 v1 = *(const float2*)(rp + 8 * DIN);
        float2 v2 = *(const float2*)(rp + 8);
        float2 v3 = *(const float2*)(rp + 8 * DIN + 8);
        af[i][0] = packh2(v0);
        af[i][1] = packh2(v1);
        af[i][2] = packh2(v2);
        af[i][3] = packh2(v3);
    }
}

// ---- fused kernel: 8 warps, 64x64 tiles, pipelined fragments ----
__global__ __launch_bounds__(256, 1)
void fused_f16p(const float* __restrict__ x,  const float* __restrict__ b1,
                const float* __restrict__ W2, const float* __restrict__ b2,
                float* __restrict__ y) {
    extern __shared__ char smem[];
    const uint32_t sb = smem_u32(smem);
    const int tid  = threadIdx.x;
    const int wid  = tid >> 5;
    const int lane = tid & 31;
    const int m       = blockIdx.y;
    const int rowBase = blockIdx.x * 128;

    float* w2s  = (float*)(smem + OFF_W2);
    float* b1s  = (float*)(smem + OFF_B1);
    float* hbuf = (float*)(smem + OFF_HBUF);

    for (int i = tid; i < NH; i += 256) b1s[i] = b1[m * NH + i];
    for (int idx = tid; idx < NH * 12; idx += 256) {
        int c = idx / 12, o = idx - c * 12;
        w2s[idx] = (o < NOUT) ? W2[(size_t)(m * NOUT + o) * DIN + m * NH + c] : 0.f;
    }
    __syncthreads();

    const int wm = wid & 1;            // 2 x 64 rows
    const int wn = wid >> 1;           // 4 x 64 cols (within 256-wide pass tile)
    const uint32_t lmoff = (uint32_t)(lane & 15) * 144u + (uint32_t)(lane >> 4) * 16u;

    // per-lane A base: row = rowBase + wm*64 + (lane>>2), col base = m*NH + 2*(lane&3)
    const float* xA = x + (size_t)(rowBase + wm * 64 + (lane >> 2)) * DIN
                    + m * NH + 2 * (lane & 3);

    // B: 256 W1 rows x 64 k = 8 cp16/thread
    auto stageB = [&](int p, int g, uint32_t buf) {
        const int k0 = g * 64;
        #pragma unroll
        for (int j = 0; j < 8; j++) {
            int f = tid + j * 256;
            int br = f >> 3, c16 = f & 7;
            const __half* src = g_w1h
                + ((size_t)(m * 512 + p * 256 + br) * 512 + k0 + c16 * 8);
            cp16(buf + T_B + (uint32_t)br * 144u + (uint32_t)c16 * 16u, src);
        }
        cp_commit();
    };
    auto ldsmB = [&](uint32_t base, int ks, uint32_t bf[4][4]) {
        #pragma unroll
        for (int jh = 0; jh < 2; jh++)
            #pragma unroll
            for (int jj = 0; jj < 2; jj++) {
                uint32_t off = (uint32_t)(wn * 64 + jh * 32 + jj * 16) * 144u
                             + (uint32_t)ks * 32u + lmoff;
                ldsm4(bf[jh * 2 + jj], base + T_B + off);
            }
    };

    ull acc2[5] = {0, 0, 0, 0, 0};

    for (int p = 0; p < 2; p++) {
        float acc[4][8][4];
        #pragma unroll
        for (int i = 0; i < 4; i++)
            #pragma unroll
            for (int j = 0; j < 8; j++)
                #pragma unroll
                for (int q = 0; q < 4; q++) acc[i][j][q] = 0.f;

        // prologue: stage B chunk 0
        stageB(p, 0, sb);
        cp_wait0();
        __syncthreads();

        for (int g = 0; g < 8; g++) {
            const uint32_t base = sb + (uint32_t)(g & 1) * STAGE_STRIDE;
            const uint32_t nbuf = sb + (uint32_t)((g + 1) & 1) * STAGE_STRIDE;
            if (g < 7) stageB(p, g + 1, nbuf);   // async, lands during MMA

            // ---- pipelined ks loop: prefetch ks+1 fragments during MMA(ks) ----
            uint32_t afb[2][4][4], bfb[2][4][4];
            loadA_frags(xA, g * 64, afb[0]);
            ldsmB(base, 0, bfb[0]);
            #pragma unroll
            for (int ks = 0; ks < 4; ks++) {
                const int cur = ks & 1, nxt = cur ^ 1;
                if (ks < 3) {
                    loadA_frags(xA, g * 64 + (ks + 1) * 16, afb[nxt]);
                    ldsmB(base, ks + 1, bfb[nxt]);
                }
                #pragma unroll
                for (int jh = 0; jh < 2; jh++)
                    #pragma unroll
                    for (int jj = 0; jj < 2; jj++) {
                        const uint32_t* rh = bfb[cur][jh * 2 + jj];
                        #pragma unroll
                        for (int i = 0; i < 4; i++) {
                            mma16816f(acc[i][jh * 4 + 2 * jj + 0], afb[cur][i], rh[0], rh[2]);
                            mma16816f(acc[i][jh * 4 + 2 * jj + 1], afb[cur][i], rh[1], rh[3]);
                        }
                    }
            }
            if (g < 7) cp_wait0();
            __syncthreads();
        }

        // ---- epilogue + fused layer 2, in two 128-col halves ----
        #pragma unroll
        for (int h2 = 0; h2 < 2; h2++) {
            if ((wn >> 1) == h2) {
                #pragma unroll
                for (int i = 0; i < 4; i++) {
                    int r0 = wm * 64 + i * 16 + (lane >> 2);
                    #pragma unroll
                    for (int jc = 0; jc < 8; jc++) {
                        int c0 = (wn & 1) * 64 + jc * 8 + 2 * (lane & 3);
                        int gc = p * 256 + h2 * 128 + c0;
                        float bb0 = b1s[gc], bb1 = b1s[gc + 1];
                        float2 v0, v1;
                        v0.x = fmaxf(acc[i][jc][0] + bb0, 0.f);
                        v0.y = fmaxf(acc[i][jc][1] + bb1, 0.f);
                        v1.x = fmaxf(acc[i][jc][2] + bb0, 0.f);
                        v1.y = fmaxf(acc[i][jc][3] + bb1, 0.f);
                        *(float2*)(hbuf + (size_t)r0 * HPITCH + c0) = v0;
                        *(float2*)(hbuf + (size_t)(r0 + 8) * HPITCH + c0) = v1;
                    }
                }
            }
            __syncthreads();
            // layer 2: 2 threads per row (even/odd cols)
            {
                const int row = tid >> 1;
                const int par = tid & 1;
                const float* hrow = hbuf + (size_t)row * HPITCH;
                #pragma unroll 8
                for (int cc = 0; cc < 64; cc++) {
                    int lc = par + 2 * cc;
                    ull hp = packdup(hrow[lc]);
                    int gc = p * 256 + h2 * 128 + lc;
                    const ull* wp = (const ull*)(w2s + (size_t)gc * 12);
                    fma2(acc2[0], hp, wp[0]);
                    fma2(acc2[1], hp, wp[1]);
                    fma2(acc2[2], hp, wp[2]);
                    fma2(acc2[3], hp, wp[3]);
                    fma2(acc2[4], hp, wp[4]);
                }
            }
            __syncthreads();
        }
    }

    // ---- reduce even/odd partner, add b2, store ----
    #pragma unroll
    for (int q5 = 0; q5 < 5; q5++)
        acc2[q5] = add2(acc2[q5], __shfl_xor_sync(0xffffffffu, acc2[q5], 1));
    if ((tid & 1) == 0) {
        const int row = tid >> 1;
        float* yp = y + (size_t)(rowBase + row) * (NM * NOUT) + m * NOUT;
        #pragma unroll
        for (int q5 = 0; q5 < 5; q5++) {
            float2 v;
            v.x = __uint_as_float((uint32_t)(acc2[q5] & 0xffffffffu)) + b2[m * NOUT + 2 * q5];
            v.y = __uint_as_float((uint32_t)(acc2[q5] >> 32)) + b2[m * NOUT + 2 * q5 + 1];
            ((float2*)yp)[q5] = v;
        }
    }
}

extern "C" void kernel_launch(void* const* d_in, const int* in_sizes, int n_in,
                              void* d_out, int out_size) {
    const float* x  = (const float*)d_in[0];
    const float* W1 = (const float*)d_in[1];
    const float* b1 = (const float*)d_in[2];
    const float* W2 = (const float*)d_in[3];
    const float* b2 = (const float*)d_in[4];
    float* y = (float*)d_out;

    cvt_w1<<<2048, 256>>>(W1);

    cudaFuncSetAttribute(fused_f16p,
                         cudaFuncAttributeMaxDynamicSharedMemorySize, SMEM_TOTAL);
    dim3 grid(8192 / 128, NM);   // 512 CTAs
    fused_f16p<<<grid, 256, SMEM_TOTAL>>>(x, b1, W2, b2, y);
}